// round 15
// baseline (speedup 1.0000x reference)
#include <cuda_runtime.h>
#include <math.h>
#include <float.h>

#define BB 32
#define UUU 1024
#define MMM 65536

// output offsets (floats)
#define R_OFF   ((size_t)0)
#define H_OFF   ((size_t)32768)
#define C_OFF   ((size_t)65536)
#define MEM_OFF ((size_t)98304)
#define WU_OFF  ((size_t)67207168)
#define WLU_OFF ((size_t)69304320)
#define WR_OFF  ((size_t)71401472)

typedef unsigned long long ull;

__device__ __forceinline__ ull fdup(float x) {
    ull r; asm("mov.b64 %0, {%1,%1};" : "=l"(r) : "f"(x)); return r;
}
__device__ __forceinline__ void ffma2(ull &d, ull a, ull b) {
    asm("fma.rn.f32x2 %0, %1, %2, %0;" : "+l"(d) : "l"(a), "l"(b));
}
__device__ __forceinline__ float2 fupk(ull v) {
    float2 f; asm("mov.b64 {%0,%1}, %2;" : "=f"(f.x), "=f"(f.y) : "l"(v)); return f;
}

// ---------------- scratch (device globals, no allocation) ----------------
__device__ float g_zp[4 * 32 * 5120];        // gate GEMM k-split partials
__device__ float g_h[BB * UUU];              // h (post-activation)
__device__ float g_hss[128];                 // partial sums of h^2
__device__ float g_hinv[BB];                 // 1/||h||
__device__ float g_pm[32 * 1024], g_ps[32 * 1024];  // softmax partials [b][block]
__device__ float g_gmax[BB], g_invden[BB];
__device__ float g_bv1[1024], g_bv2[1024], g_bmv[1024];
__device__ int   g_bmi[1024];
__device__ float g_nth[BB];
__device__ int   g_si[1];
__device__ float g_rp[(size_t)128 * BB * UUU]; // r split-K partials

__device__ __forceinline__ float hsig(float v) {
    return fminf(fmaxf(0.2f * v + 0.5f, 0.0f), 1.0f);
}

// ---------------- K1: gate GEMMs (x@W + h@R1 fused; r@R2), k-split 4 ----------------
__global__ __launch_bounds__(256) void k_gemm(
    const float* __restrict__ x, const float* __restrict__ h,
    const float* __restrict__ r, const float* __restrict__ W,
    const float* __restrict__ RK, const float* __restrict__ bias)
{
    __shared__ ull A2[32 * 34];                   // dup-packed A
    __shared__ __align__(16) float W_s[32][132];
    int jb = blockIdx.x >> 2;
    int ks = blockIdx.x & 3;
    int t = threadIdx.x;
    int b0 = (t >> 5) * 4;
    int j0 = (t & 31) * 4;
    int jbase = jb * 128;

    ull accp[4][2];
#pragma unroll
    for (int i = 0; i < 4; i++) { accp[i][0] = 0ULL; accp[i][1] = 0ULL; }

    int nsrc = (jb < 32) ? 2 : 1;
    int kbase = ks * 256;
    for (int s = 0; s < nsrc; s++) {
        const float* A; const float* Wm; int ldw;
        if (jb < 32) {
            if (s == 0) { A = x; Wm = W;  ldw = 4096; }
            else        { A = h; Wm = RK; ldw = 5120; }
        } else          { A = r; Wm = RK; ldw = 5120; }

        for (int kc = 0; kc < 256; kc += 32) {
#pragma unroll
            for (int i = 0; i < 4; i++) {
                int e = t + i * 256;
                A2[(e >> 5) * 34 + (e & 31)] =
                    fdup(A[(e >> 5) * 1024 + kbase + kc + (e & 31)]);
            }
#pragma unroll
            for (int i = 0; i < 16; i++) {
                int e = t + i * 256;
                int kk = e >> 7, j = e & 127;
                W_s[kk][j] = Wm[(size_t)(kbase + kc + kk) * ldw + jbase + j];
            }
            __syncthreads();
#pragma unroll
            for (int kk = 0; kk < 32; kk++) {
                ull wp0 = *(const ull*)&W_s[kk][j0];
                ull wp1 = *(const ull*)&W_s[kk][j0 + 2];
#pragma unroll
                for (int i = 0; i < 4; i++) {
                    ull ad = A2[(b0 + i) * 34 + kk];
                    ffma2(accp[i][0], ad, wp0);
                    ffma2(accp[i][1], ad, wp1);
                }
            }
            __syncthreads();
        }
    }
#pragma unroll
    for (int i = 0; i < 4; i++) {
#pragma unroll
        for (int jp = 0; jp < 2; jp++) {
            float2 f = fupk(accp[i][jp]);
            int j = jbase + j0 + jp * 2;
            float v0 = f.x, v1 = f.y;
            if (ks == 0 && jb < 32) { v0 += bias[j]; v1 += bias[j + 1]; }
            g_zp[((ks * 32) + (b0 + i)) * 5120 + j]     = v0;
            g_zp[((ks * 32) + (b0 + i)) * 5120 + j + 1] = v1;
        }
    }
}

// ---------------- K2: reduce partials, activations, h, c, h^2 partials ----------------
__global__ __launch_bounds__(256) void k_gates(const float* __restrict__ c_tm1,
                                               float* __restrict__ out)
{
    int blk = blockIdx.x;            // 128
    int b = blk >> 2, uc = blk & 3;
    int u = uc * 256 + threadIdx.x;
    float zi = 0, zf = 0, zc = 0, zo = 0, ri = 0;
#pragma unroll
    for (int s = 0; s < 4; s++) {
        const float* p = &g_zp[(s * 32 + b) * 5120];
        zi += p[u]; zf += p[1024 + u]; zc += p[2048 + u]; zo += p[3072 + u]; ri += p[4096 + u];
    }
    float ig = hsig(zi + ri), fg = hsig(zf), og = hsig(zo);
    float c = fg * c_tm1[b * 1024 + u] + ig * tanhf(zc);
    float hh = og * tanhf(c);
    out[C_OFF + b * 1024 + u] = c;
    out[H_OFF + b * 1024 + u] = hh;
    g_h[b * 1024 + u] = hh;

    __shared__ float red[256];
    red[threadIdx.x] = hh * hh;
    __syncthreads();
    for (int s = 128; s > 0; s >>= 1) {
        if (threadIdx.x < s) red[threadIdx.x] += red[threadIdx.x + s];
        __syncthreads();
    }
    if (threadIdx.x == 0) g_hss[blk] = red[0];
}

__global__ void k_hinv() {
    int b = threadIdx.x;
    if (b < 32) {
        float s = g_hss[b * 4] + g_hss[b * 4 + 1] + g_hss[b * 4 + 2] + g_hss[b * 4 + 3];
        g_hinv[b] = rsqrtf(fmaxf(s, 1e-12f));
    }
}

// ---------------- K4: fused membank pass (dots + ss + mem_new + softmax partials) ----
// layout: ww_f (float[32*132]) | h_s (float[32*132]) | mb_s (float[64*132])
#define K4_STR 132
#define K4_SMEM ((32*K4_STR + 32*K4_STR + 64*K4_STR) * 4)

__global__ __launch_bounds__(256, 2) void k_sim_mem(const float* __restrict__ mb,
                                                    const float* __restrict__ wr_prev,
                                                    const float* __restrict__ wlu,
                                                    const float* __restrict__ wg,
                                                    float* __restrict__ out)
{
    extern __shared__ __align__(16) char smem_raw[];
    float* ww_f = (float*)smem_raw;                                    // [32][132] plain
    float* h_s  = (float*)(smem_raw + 32 * K4_STR * 4);                // [32][132]
    float* mb_s = (float*)(smem_raw + 64 * K4_STR * 4);                // [64][132]
    float* red    = mb_s;                                              // alias (epilogue)
    float* ss_red = mb_s + 128 * 17;
    float* pmx    = mb_s + 2304;                                       // [32][16]
    float* psx    = mb_s + 2304 + 512;                                 // [32][16]

    int m0 = blockIdx.x * 64;
    int t = threadIdx.x;

    // ww fill: plain floats, [32 b][128 m] (only first 128 of 132 cols used)
    float sg = 1.0f / (1.0f + expf(-wg[0]));
#pragma unroll
    for (int i = 0; i < 8; i++) {
        int e = t + i * 256;
        int b = e >> 6, m = e & 63;
        size_t gi = (size_t)b * 65536 + m0 + m;
        ww_f[b * K4_STR + m] = sg * wr_prev[gi] + (1.0f - sg) * wlu[gi];
    }

    int tl = t & 127, us = t >> 7;
    int bg = tl & 7, mg = tl >> 3;      // dots: b rows bg+{0,8,16,24}, m rows mg+{0,16,32,48}
    int ug2 = t & 31, mg8 = t >> 5;     // memnew: m rows mg8*8+{0..7}, u cols ug2*4+{0..3}

    ull dotp[4][4];
    ull ssp[4];
#pragma unroll
    for (int i = 0; i < 4; i++) {
#pragma unroll
        for (int j = 0; j < 4; j++) dotp[i][j] = 0ULL;
        ssp[i] = 0ULL;
    }

    for (int uc = 0; uc < 1024; uc += 128) {
        __syncthreads();
        // fill h_s [32][128]
#pragma unroll
        for (int i = 0; i < 4; i++) {
            int f = t + i * 256;
            int row = f >> 5, c = (f & 31) * 4;
            *(float4*)&h_s[row * K4_STR + c] = *(const float4*)&g_h[row * 1024 + uc + c];
        }
        // fill mb_s [64][128]
#pragma unroll
        for (int i = 0; i < 8; i++) {
            int f = t + i * 256;
            int row = f >> 5, c = (f & 31) * 4;
            *(float4*)&mb_s[row * K4_STR + c] =
                *(const float4*)&mb[(size_t)(m0 + row) * 1024 + uc + c];
        }
        __syncthreads();

        // ---- dots: each thread 4b x 4m, its u-half (16 of 32 u4-steps) ----
#pragma unroll 4
        for (int u4 = us * 16; u4 < us * 16 + 16; u4++) {
            ulonglong2 hp[4], mp[4];
#pragma unroll
            for (int bi = 0; bi < 4; bi++)
                hp[bi] = *(const ulonglong2*)&h_s[(bg + bi * 8) * K4_STR + u4 * 4];
#pragma unroll
            for (int mi = 0; mi < 4; mi++)
                mp[mi] = *(const ulonglong2*)&mb_s[(mg + mi * 16) * K4_STR + u4 * 4];
#pragma unroll
            for (int bi = 0; bi < 4; bi++)
#pragma unroll
                for (int mi = 0; mi < 4; mi++) {
                    ffma2(dotp[bi][mi], hp[bi].x, mp[mi].x);
                    ffma2(dotp[bi][mi], hp[bi].y, mp[mi].y);
                }
            if (bg == 0) {
#pragma unroll
                for (int mi = 0; mi < 4; mi++) {
                    ffma2(ssp[mi], mp[mi].x, mp[mi].x);
                    ffma2(ssp[mi], mp[mi].y, mp[mi].y);
                }
            }
        }

        // ---- mem_new: each thread 8m x 4u; ww = 2 uniform float4 loads + fdup ----
        ull acc[8][2];
#pragma unroll
        for (int mi = 0; mi < 8; mi++) {
            ulonglong2 a = *(const ulonglong2*)&mb_s[(mg8 * 8 + mi) * K4_STR + ug2 * 4];
            acc[mi][0] = a.x; acc[mi][1] = a.y;
        }
#pragma unroll 4
        for (int b = 0; b < 32; b++) {
            float4 w0 = *(const float4*)&ww_f[b * K4_STR + mg8 * 8];
            float4 w1 = *(const float4*)&ww_f[b * K4_STR + mg8 * 8 + 4];
            ull wd0 = fdup(w0.x), wd1 = fdup(w0.y), wd2 = fdup(w0.z), wd3 = fdup(w0.w);
            ull wd4 = fdup(w1.x), wd5 = fdup(w1.y), wd6 = fdup(w1.z), wd7 = fdup(w1.w);
            ulonglong2 hh = *(const ulonglong2*)&h_s[b * K4_STR + ug2 * 4];
            ffma2(acc[0][0], wd0, hh.x); ffma2(acc[0][1], wd0, hh.y);
            ffma2(acc[1][0], wd1, hh.x); ffma2(acc[1][1], wd1, hh.y);
            ffma2(acc[2][0], wd2, hh.x); ffma2(acc[2][1], wd2, hh.y);
            ffma2(acc[3][0], wd3, hh.x); ffma2(acc[3][1], wd3, hh.y);
            ffma2(acc[4][0], wd4, hh.x); ffma2(acc[4][1], wd4, hh.y);
            ffma2(acc[5][0], wd5, hh.x); ffma2(acc[5][1], wd5, hh.y);
            ffma2(acc[6][0], wd6, hh.x); ffma2(acc[6][1], wd6, hh.y);
            ffma2(acc[7][0], wd7, hh.x); ffma2(acc[7][1], wd7, hh.y);
        }
#pragma unroll
        for (int mi = 0; mi < 8; mi++) {
            size_t o = MEM_OFF + (size_t)(m0 + mg8 * 8 + mi) * 1024 + uc + ug2 * 4;
            ulonglong2 s; s.x = acc[mi][0]; s.y = acc[mi][1];
            *(ulonglong2*)&out[o] = s;
        }
    }

    // ---- epilogue: combine u-halves, normalize, store sim, softmax partials ----
    __syncthreads();
    float dsum[16], ssv[4];
#pragma unroll
    for (int bi = 0; bi < 4; bi++)
#pragma unroll
        for (int mi = 0; mi < 4; mi++) {
            float2 f = fupk(dotp[bi][mi]);
            dsum[bi * 4 + mi] = f.x + f.y;
        }
#pragma unroll
    for (int mi = 0; mi < 4; mi++) {
        float2 f = fupk(ssp[mi]);
        ssv[mi] = f.x + f.y;
    }
    if (us == 1) {
#pragma unroll
        for (int k = 0; k < 16; k++) red[tl * 17 + k] = dsum[k];
        if (bg == 0) {
#pragma unroll
            for (int mi = 0; mi < 4; mi++) ss_red[mg + mi * 16] = ssv[mi];
        }
    }
    __syncthreads();
    if (us == 0) {
#pragma unroll
        for (int k = 0; k < 16; k++) dsum[k] += red[tl * 17 + k];
        if (bg == 0) {
#pragma unroll
            for (int mi = 0; mi < 4; mi++) {
                float s = ss_red[mg + mi * 16] + ssv[mi];
                ss_red[mg + mi * 16] = rsqrtf(fmaxf(s, 1e-12f));
            }
        }
    }
    __syncthreads();
    if (us == 0) {
#pragma unroll
        for (int bi = 0; bi < 4; bi++) {
            int b = bg + bi * 8;
            float hinv = g_hinv[b];
            float v[4];
#pragma unroll
            for (int mi = 0; mi < 4; mi++) {
                int m = mg + mi * 16;
                v[mi] = dsum[bi * 4 + mi] * hinv * ss_red[m];
                out[WR_OFF + (size_t)b * 65536 + m0 + m] = v[mi];
            }
            float pm_t = fmaxf(fmaxf(v[0], v[1]), fmaxf(v[2], v[3]));
            float s_t = expf(v[0] - pm_t) + expf(v[1] - pm_t) +
                        expf(v[2] - pm_t) + expf(v[3] - pm_t);
            pmx[b * 16 + mg] = pm_t;
            psx[b * 16 + mg] = s_t;
        }
    }
    __syncthreads();
    if (t < 32) {
        float pm = -FLT_MAX;
#pragma unroll
        for (int q = 0; q < 16; q++) pm = fmaxf(pm, pmx[t * 16 + q]);
        float s = 0.0f;
#pragma unroll
        for (int q = 0; q < 16; q++) s += psx[t * 16 + q] * expf(pmx[t * 16 + q] - pm);
        g_pm[t * 1024 + blockIdx.x] = pm;
        g_ps[t * 1024 + blockIdx.x] = s;
    }
}

// ---------------- K5: softmax combine (grid 32, one block per b) ----------------
__global__ __launch_bounds__(256) void k_red2()
{
    int b = blockIdx.x;
    int t = threadIdx.x;
    __shared__ float red[256];
    float pm = -FLT_MAX;
#pragma unroll
    for (int k = 0; k < 4; k++)
        pm = fmaxf(pm, g_pm[b * 1024 + t + k * 256]);
    red[t] = pm; __syncthreads();
    for (int st = 128; st > 0; st >>= 1) {
        if (t < st) red[t] = fmaxf(red[t], red[t + st]);
        __syncthreads();
    }
    float gm = red[0];
    __syncthreads();
    float s = 0.0f;
#pragma unroll
    for (int k = 0; k < 4; k++) {
        int idx = b * 1024 + t + k * 256;
        s += g_ps[idx] * expf(g_pm[idx] - gm);
    }
    red[t] = s; __syncthreads();
    for (int st = 128; st > 0; st >>= 1) {
        if (t < st) red[t] += red[t + st];
        __syncthreads();
    }
    if (t == 0) { g_gmax[b] = gm; g_invden[b] = 1.0f / red[0]; }
}

// ---------------- K6: wr (in place over sim), wu_new, order-stat partials ----------------
__global__ __launch_bounds__(256) void k_wr_wu(const float* __restrict__ wu,
                                               const float* __restrict__ wlu,
                                               const float* __restrict__ wr_prev,
                                               const float* __restrict__ wg,
                                               float* __restrict__ out)
{
    int blk = blockIdx.x;             // 1024 = 32 b x 32 chunks
    int b = blk >> 5, mc = blk & 31;
    int t = threadIdx.x;
    size_t base = (size_t)b * 65536 + (size_t)mc * 2048 + (size_t)t * 8;
    float sg = 1.0f / (1.0f + expf(-wg[0]));
    float gm = g_gmax[b], inv = g_invden[b];

    float s1 = FLT_MAX, s2 = FLT_MAX;
    float mv = FLT_MAX; int mi_ = 0x7fffffff;
#pragma unroll
    for (int k = 0; k < 8; k++) {
        size_t idx = base + k;
        float sim = out[WR_OFF + idx];
        float wr = expf(sim - gm) * inv;
        out[WR_OFF + idx] = wr;
        float ww = sg * wr_prev[idx] + (1.0f - sg) * wlu[idx];
        float wun = 0.5f * wu[idx] + wr + ww;
        out[WU_OFF + idx] = wun;
        if (wun < s1) { s2 = s1; s1 = wun; }
        else if (wun < s2) { s2 = wun; }
        int m = (int)(idx - (size_t)b * 65536);
        if (wun < mv || (wun == mv && m < mi_)) { mv = wun; mi_ = m; }
    }
    __shared__ float r1[256], r2[256], rv[256];
    __shared__ int ri_[256];
    r1[t] = s1; r2[t] = s2; rv[t] = mv; ri_[t] = mi_;
    __syncthreads();
    for (int st = 128; st > 0; st >>= 1) {
        if (t < st) {
            float b1 = r1[t + st], b2 = r2[t + st];
            float a1 = r1[t], a2 = r2[t];
            if (b1 < a1) { a2 = fminf(a1, b2); a1 = b1; }
            else         { a2 = fminf(a2, b1); }
            r1[t] = a1; r2[t] = a2;
            float bv = rv[t + st]; int bi2 = ri_[t + st];
            if (bv < rv[t] || (bv == rv[t] && bi2 < ri_[t])) { rv[t] = bv; ri_[t] = bi2; }
        }
        __syncthreads();
    }
    if (t == 0) { g_bv1[blk] = r1[0]; g_bv2[blk] = r2[0]; g_bmv[blk] = rv[0]; g_bmi[blk] = ri_[0]; }
}

__global__ void k_redmin()
{
    int b = threadIdx.x;
    __shared__ int sidx[32];
    if (b < 32) {
        float s1 = FLT_MAX, s2 = FLT_MAX;
        float mv = FLT_MAX; int mi_ = 0x7fffffff;
        for (int p = 0; p < 32; p++) {
            int blk = b * 32 + p;
            float b1 = g_bv1[blk], b2 = g_bv2[blk];
            if (b1 < s1) { s2 = fminf(s1, b2); s1 = b1; }
            else         { s2 = fminf(s2, b1); }
            float bv = g_bmv[blk]; int bi2 = g_bmi[blk];
            if (bv < mv || (bv == mv && bi2 < mi_)) { mv = bv; mi_ = bi2; }
        }
        g_nth[b] = s2;
        sidx[b] = mi_;
    }
    __syncthreads();
    if (b == 0) {
        int m = sidx[0];
        for (int i = 1; i < 32; i++) m = min(m, sidx[i]);
        g_si[0] = m;
    }
}

// ---------------- K7: wlu_new ----------------
__global__ __launch_bounds__(256) void k_wlu(float* __restrict__ out)
{
    int blk = blockIdx.x;
    int b = blk >> 5, mc = blk & 31;
    size_t base = (size_t)b * 65536 + (size_t)mc * 2048 + (size_t)threadIdx.x * 8;
    float nth = g_nth[b];
#pragma unroll
    for (int k = 0; k < 8; k++)
        out[WLU_OFF + base + k] = (out[WU_OFF + base + k] <= nth) ? 1.0f : 0.0f;
}

// ---------------- K8: keep-row fixup on mem_new ----------------
__global__ void k_fixrow(const float* __restrict__ mb, float* __restrict__ out)
{
    int m = g_si[0];
    for (int u = threadIdx.x; u < 1024; u += blockDim.x)
        out[MEM_OFF + (size_t)m * 1024 + u] -= mb[(size_t)m * 1024 + u];
}

// ---------------- K9: r = wr @ membank (split-K), 8b x 4u tile, grid 512 -------------
__global__ __launch_bounds__(256, 3) void k_r(const float* __restrict__ mb,
                                              const float* __restrict__ out)
{
    __shared__ __align__(16) float wr_t[64][36];   // 144B stride, 16-aligned
    int slice = blockIdx.x >> 2;
    int ut = blockIdx.x & 3;
    int t = threadIdx.x;
    int tu = t & 63;
    int b0 = (t >> 6) * 8;
    int u = ut * 256 + tu * 4;
    int mbase = slice * 512;

    ull accp[4][4];
#pragma unroll
    for (int i = 0; i < 4; i++)
#pragma unroll
        for (int j = 0; j < 4; j++) accp[i][j] = 0ULL;

    for (int mc = 0; mc < 512; mc += 64) {
#pragma unroll
        for (int i = 0; i < 8; i++) {
            int e = t + i * 256;
            int b = e >> 6, mm = e & 63;
            wr_t[mm][b] = out[WR_OFF + (size_t)b * 65536 + mbase + mc + mm];
        }
        __syncthreads();
#pragma unroll 8
        for (int mm = 0; mm < 64; mm++) {
            float4 v = *(const float4*)&mb[(size_t)(mbase + mc + mm) * 1024 + u];
            ull vd0 = fdup(v.x), vd1 = fdup(v.y), vd2 = fdup(v.z), vd3 = fdup(v.w);
            ulonglong2 w01 = *(const ulonglong2*)&wr_t[mm][b0];
            ulonglong2 w23 = *(const ulonglong2*)&wr_t[mm][b0 + 4];
            ffma2(accp[0][0], w01.x, vd0); ffma2(accp[0][1], w01.x, vd1);
            ffma2(accp[0][2], w01.x, vd2); ffma2(accp[0][3], w01.x, vd3);
            ffma2(accp[1][0], w01.y, vd0); ffma2(accp[1][1], w01.y, vd1);
            ffma2(accp[1][2], w01.y, vd2); ffma2(accp[1][3], w01.y, vd3);
            ffma2(accp[2][0], w23.x, vd0); ffma2(accp[2][1], w23.x, vd1);
            ffma2(accp[2][2], w23.x, vd2); ffma2(accp[2][3], w23.x, vd3);
            ffma2(accp[3][0], w23.y, vd0); ffma2(accp[3][1], w23.y, vd1);
            ffma2(accp[3][2], w23.y, vd2); ffma2(accp[3][3], w23.y, vd3);
        }
        __syncthreads();
    }
#pragma unroll
    for (int bp = 0; bp < 4; bp++) {
        float2 f0 = fupk(accp[bp][0]), f1 = fupk(accp[bp][1]);
        float2 f2 = fupk(accp[bp][2]), f3 = fupk(accp[bp][3]);
        size_t base = ((size_t)slice * 32 + b0 + bp * 2) * 1024 + u;
        *(float4*)&g_rp[base]        = make_float4(f0.x, f1.x, f2.x, f3.x);
        *(float4*)&g_rp[base + 1024] = make_float4(f0.y, f1.y, f2.y, f3.y);
    }
}

__global__ __launch_bounds__(256) void k_rred(float* __restrict__ out)
{
    int idx = blockIdx.x * 256 + threadIdx.x;   // 0..32767
    float s = 0;
    for (int sl = 0; sl < 128; sl++) s += g_rp[(size_t)sl * 32768 + idx];
    out[R_OFF + idx] = s;
}

// ---------------- launcher ----------------
extern "C" void kernel_launch(void* const* d_in, const int* in_sizes, int n_in,
                              void* d_out, int out_size)
{
    const float* x        = (const float*)d_in[0];
    const float* h_tm1    = (const float*)d_in[1];
    const float* c_tm1    = (const float*)d_in[2];
    const float* r_tm1    = (const float*)d_in[3];
    const float* membank  = (const float*)d_in[4];
    const float* wu       = (const float*)d_in[5];
    const float* wlu      = (const float*)d_in[6];
    const float* wr_prev  = (const float*)d_in[7];
    const float* Wk       = (const float*)d_in[8];
    const float* RK       = (const float*)d_in[9];
    const float* bias     = (const float*)d_in[10];
    const float* wgate    = (const float*)d_in[11];
    float* out = (float*)d_out;

    cudaFuncSetAttribute(k_sim_mem, cudaFuncAttributeMaxDynamicSharedMemorySize, K4_SMEM);

    k_gemm<<<160, 256>>>(x, h_tm1, r_tm1, Wk, RK, bias);
    k_gates<<<128, 256>>>(c_tm1, out);
    k_hinv<<<1, 32>>>();
    k_sim_mem<<<1024, 256, K4_SMEM>>>(membank, wr_prev, wlu, wgate, out);
    k_red2<<<32, 256>>>();
    k_wr_wu<<<1024, 256>>>(wu, wlu, wr_prev, wgate, out);
    k_redmin<<<1, 32>>>();
    k_wlu<<<1024, 256>>>(out);
    k_fixrow<<<1, 256>>>(membank, out);
    k_r<<<512, 256>>>(membank, out);
    k_rred<<<128, 256>>>(out);
}

// round 16
// speedup vs baseline: 1.1245x; 1.1245x over previous
#include <cuda_runtime.h>
#include <math.h>
#include <float.h>

#define BB 32
#define UUU 1024
#define MMM 65536

// output offsets (floats)
#define R_OFF   ((size_t)0)
#define H_OFF   ((size_t)32768)
#define C_OFF   ((size_t)65536)
#define MEM_OFF ((size_t)98304)
#define WU_OFF  ((size_t)67207168)
#define WLU_OFF ((size_t)69304320)
#define WR_OFF  ((size_t)71401472)

typedef unsigned long long ull;

__device__ __forceinline__ ull fdup(float x) {
    ull r; asm("mov.b64 %0, {%1,%1};" : "=l"(r) : "f"(x)); return r;
}
__device__ __forceinline__ void ffma2(ull &d, ull a, ull b) {
    asm("fma.rn.f32x2 %0, %1, %2, %0;" : "+l"(d) : "l"(a), "l"(b));
}
__device__ __forceinline__ float2 fupk(ull v) {
    float2 f; asm("mov.b64 {%0,%1}, %2;" : "=f"(f.x), "=f"(f.y) : "l"(v)); return f;
}

// ---------------- scratch (device globals, no allocation) ----------------
__device__ float g_zp[4 * 32 * 5120];        // gate GEMM k-split partials
__device__ float g_h[BB * UUU];              // h (post-activation)
__device__ float g_hss[128];                 // partial sums of h^2
__device__ float g_hinv[BB];                 // 1/||h||
__device__ float g_pm[32 * 1024], g_ps[32 * 1024];  // softmax partials [b][block]
__device__ float g_gmax[BB], g_invden[BB];
__device__ float g_bv1[1024], g_bv2[1024], g_bmv[1024];
__device__ int   g_bmi[1024];
__device__ float g_nth[BB];
__device__ int   g_si[1];
__device__ float g_rp[(size_t)128 * BB * UUU]; // r split-K partials

__device__ __forceinline__ float hsig(float v) {
    return fminf(fmaxf(0.2f * v + 0.5f, 0.0f), 1.0f);
}

// ---------------- K1: gate GEMMs (x@W + h@R1 fused; r@R2), k-split 4 ----------------
__global__ __launch_bounds__(256) void k_gemm(
    const float* __restrict__ x, const float* __restrict__ h,
    const float* __restrict__ r, const float* __restrict__ W,
    const float* __restrict__ RK, const float* __restrict__ bias)
{
    __shared__ ull A2[32 * 34];                   // dup-packed A
    __shared__ __align__(16) float W_s[32][132];
    int jb = blockIdx.x >> 2;
    int ks = blockIdx.x & 3;
    int t = threadIdx.x;
    int b0 = (t >> 5) * 4;
    int j0 = (t & 31) * 4;
    int jbase = jb * 128;

    ull accp[4][2];
#pragma unroll
    for (int i = 0; i < 4; i++) { accp[i][0] = 0ULL; accp[i][1] = 0ULL; }

    int nsrc = (jb < 32) ? 2 : 1;
    int kbase = ks * 256;
    for (int s = 0; s < nsrc; s++) {
        const float* A; const float* Wm; int ldw;
        if (jb < 32) {
            if (s == 0) { A = x; Wm = W;  ldw = 4096; }
            else        { A = h; Wm = RK; ldw = 5120; }
        } else          { A = r; Wm = RK; ldw = 5120; }

        for (int kc = 0; kc < 256; kc += 32) {
#pragma unroll
            for (int i = 0; i < 4; i++) {
                int e = t + i * 256;
                A2[(e >> 5) * 34 + (e & 31)] =
                    fdup(A[(e >> 5) * 1024 + kbase + kc + (e & 31)]);
            }
#pragma unroll
            for (int i = 0; i < 16; i++) {
                int e = t + i * 256;
                int kk = e >> 7, j = e & 127;
                W_s[kk][j] = Wm[(size_t)(kbase + kc + kk) * ldw + jbase + j];
            }
            __syncthreads();
#pragma unroll
            for (int kk = 0; kk < 32; kk++) {
                ull wp0 = *(const ull*)&W_s[kk][j0];
                ull wp1 = *(const ull*)&W_s[kk][j0 + 2];
#pragma unroll
                for (int i = 0; i < 4; i++) {
                    ull ad = A2[(b0 + i) * 34 + kk];
                    ffma2(accp[i][0], ad, wp0);
                    ffma2(accp[i][1], ad, wp1);
                }
            }
            __syncthreads();
        }
    }
#pragma unroll
    for (int i = 0; i < 4; i++) {
#pragma unroll
        for (int jp = 0; jp < 2; jp++) {
            float2 f = fupk(accp[i][jp]);
            int j = jbase + j0 + jp * 2;
            float v0 = f.x, v1 = f.y;
            if (ks == 0 && jb < 32) { v0 += bias[j]; v1 += bias[j + 1]; }
            g_zp[((ks * 32) + (b0 + i)) * 5120 + j]     = v0;
            g_zp[((ks * 32) + (b0 + i)) * 5120 + j + 1] = v1;
        }
    }
}

// ---------------- K2: reduce partials, activations, h, c, h^2 partials ----------------
__global__ __launch_bounds__(256) void k_gates(const float* __restrict__ c_tm1,
                                               float* __restrict__ out)
{
    int blk = blockIdx.x;            // 128
    int b = blk >> 2, uc = blk & 3;
    int u = uc * 256 + threadIdx.x;
    float zi = 0, zf = 0, zc = 0, zo = 0, ri = 0;
#pragma unroll
    for (int s = 0; s < 4; s++) {
        const float* p = &g_zp[(s * 32 + b) * 5120];
        zi += p[u]; zf += p[1024 + u]; zc += p[2048 + u]; zo += p[3072 + u]; ri += p[4096 + u];
    }
    float ig = hsig(zi + ri), fg = hsig(zf), og = hsig(zo);
    float c = fg * c_tm1[b * 1024 + u] + ig * tanhf(zc);
    float hh = og * tanhf(c);
    out[C_OFF + b * 1024 + u] = c;
    out[H_OFF + b * 1024 + u] = hh;
    g_h[b * 1024 + u] = hh;

    __shared__ float red[256];
    red[threadIdx.x] = hh * hh;
    __syncthreads();
    for (int s = 128; s > 0; s >>= 1) {
        if (threadIdx.x < s) red[threadIdx.x] += red[threadIdx.x + s];
        __syncthreads();
    }
    if (threadIdx.x == 0) g_hss[blk] = red[0];
}

__global__ void k_hinv() {
    int b = threadIdx.x;
    if (b < 32) {
        float s = g_hss[b * 4] + g_hss[b * 4 + 1] + g_hss[b * 4 + 2] + g_hss[b * 4 + 3];
        g_hinv[b] = rsqrtf(fmaxf(s, 1e-12f));
    }
}

// ---------------- K4: fused membank pass (dots + ss + mem_new + softmax partials) ----
// layout: ww_f (float[32*132]) | h_s (float[32*132]) | mb_s (float[64*132])
#define K4_STR 132
#define K4_SMEM ((32*K4_STR + 32*K4_STR + 64*K4_STR) * 4)

__global__ __launch_bounds__(256, 2) void k_sim_mem(const float* __restrict__ mb,
                                                    const float* __restrict__ wr_prev,
                                                    const float* __restrict__ wlu,
                                                    const float* __restrict__ wg,
                                                    float* __restrict__ out)
{
    extern __shared__ __align__(16) char smem_raw[];
    float* ww_f = (float*)smem_raw;                                    // [32][132] plain
    float* h_s  = (float*)(smem_raw + 32 * K4_STR * 4);                // [32][132]
    float* mb_s = (float*)(smem_raw + 64 * K4_STR * 4);                // [64][132]
    float* red    = mb_s;                                              // alias (epilogue)
    float* ss_red = mb_s + 128 * 17;
    float* pmx    = mb_s + 2304;                                       // [32][16]
    float* psx    = mb_s + 2304 + 512;                                 // [32][16]

    int m0 = blockIdx.x * 64;
    int t = threadIdx.x;

    // ww fill: plain floats, [32 b][128 m] (only first 128 of 132 cols used)
    float sg = 1.0f / (1.0f + expf(-wg[0]));
#pragma unroll
    for (int i = 0; i < 8; i++) {
        int e = t + i * 256;
        int b = e >> 6, m = e & 63;
        size_t gi = (size_t)b * 65536 + m0 + m;
        ww_f[b * K4_STR + m] = sg * wr_prev[gi] + (1.0f - sg) * wlu[gi];
    }

    int tl = t & 127, us = t >> 7;
    int bg = tl & 7, mg = tl >> 3;      // dots: b rows bg+{0,8,16,24}, m rows mg+{0,16,32,48}
    int ug2 = t & 31, mg8 = t >> 5;     // memnew: m rows mg8*8+{0..7}, u cols ug2*4+{0..3}

    ull dotp[4][4];
    ull ssp[4];
#pragma unroll
    for (int i = 0; i < 4; i++) {
#pragma unroll
        for (int j = 0; j < 4; j++) dotp[i][j] = 0ULL;
        ssp[i] = 0ULL;
    }

    for (int uc = 0; uc < 1024; uc += 128) {
        __syncthreads();
        // fill h_s [32][128]
#pragma unroll
        for (int i = 0; i < 4; i++) {
            int f = t + i * 256;
            int row = f >> 5, c = (f & 31) * 4;
            *(float4*)&h_s[row * K4_STR + c] = *(const float4*)&g_h[row * 1024 + uc + c];
        }
        // fill mb_s [64][128]
#pragma unroll
        for (int i = 0; i < 8; i++) {
            int f = t + i * 256;
            int row = f >> 5, c = (f & 31) * 4;
            *(float4*)&mb_s[row * K4_STR + c] =
                *(const float4*)&mb[(size_t)(m0 + row) * 1024 + uc + c];
        }
        __syncthreads();

        // ---- dots: each thread 4b x 4m, its u-half (16 of 32 u4-steps) ----
#pragma unroll 4
        for (int u4 = us * 16; u4 < us * 16 + 16; u4++) {
            ulonglong2 hp[4], mp[4];
#pragma unroll
            for (int bi = 0; bi < 4; bi++)
                hp[bi] = *(const ulonglong2*)&h_s[(bg + bi * 8) * K4_STR + u4 * 4];
#pragma unroll
            for (int mi = 0; mi < 4; mi++)
                mp[mi] = *(const ulonglong2*)&mb_s[(mg + mi * 16) * K4_STR + u4 * 4];
#pragma unroll
            for (int bi = 0; bi < 4; bi++)
#pragma unroll
                for (int mi = 0; mi < 4; mi++) {
                    ffma2(dotp[bi][mi], hp[bi].x, mp[mi].x);
                    ffma2(dotp[bi][mi], hp[bi].y, mp[mi].y);
                }
            if (bg == 0) {
#pragma unroll
                for (int mi = 0; mi < 4; mi++) {
                    ffma2(ssp[mi], mp[mi].x, mp[mi].x);
                    ffma2(ssp[mi], mp[mi].y, mp[mi].y);
                }
            }
        }

        // ---- mem_new: each thread 8m x 4u; ww = 2 uniform float4 loads + fdup ----
        ull acc[8][2];
#pragma unroll
        for (int mi = 0; mi < 8; mi++) {
            ulonglong2 a = *(const ulonglong2*)&mb_s[(mg8 * 8 + mi) * K4_STR + ug2 * 4];
            acc[mi][0] = a.x; acc[mi][1] = a.y;
        }
#pragma unroll 4
        for (int b = 0; b < 32; b++) {
            float4 w0 = *(const float4*)&ww_f[b * K4_STR + mg8 * 8];
            float4 w1 = *(const float4*)&ww_f[b * K4_STR + mg8 * 8 + 4];
            ull wd0 = fdup(w0.x), wd1 = fdup(w0.y), wd2 = fdup(w0.z), wd3 = fdup(w0.w);
            ull wd4 = fdup(w1.x), wd5 = fdup(w1.y), wd6 = fdup(w1.z), wd7 = fdup(w1.w);
            ulonglong2 hh = *(const ulonglong2*)&h_s[b * K4_STR + ug2 * 4];
            ffma2(acc[0][0], wd0, hh.x); ffma2(acc[0][1], wd0, hh.y);
            ffma2(acc[1][0], wd1, hh.x); ffma2(acc[1][1], wd1, hh.y);
            ffma2(acc[2][0], wd2, hh.x); ffma2(acc[2][1], wd2, hh.y);
            ffma2(acc[3][0], wd3, hh.x); ffma2(acc[3][1], wd3, hh.y);
            ffma2(acc[4][0], wd4, hh.x); ffma2(acc[4][1], wd4, hh.y);
            ffma2(acc[5][0], wd5, hh.x); ffma2(acc[5][1], wd5, hh.y);
            ffma2(acc[6][0], wd6, hh.x); ffma2(acc[6][1], wd6, hh.y);
            ffma2(acc[7][0], wd7, hh.x); ffma2(acc[7][1], wd7, hh.y);
        }
#pragma unroll
        for (int mi = 0; mi < 8; mi++) {
            size_t o = MEM_OFF + (size_t)(m0 + mg8 * 8 + mi) * 1024 + uc + ug2 * 4;
            ulonglong2 s; s.x = acc[mi][0]; s.y = acc[mi][1];
            *(ulonglong2*)&out[o] = s;
        }
    }

    // ---- epilogue: combine u-halves, normalize, store sim, softmax partials ----
    __syncthreads();
    float dsum[16], ssv[4];
#pragma unroll
    for (int bi = 0; bi < 4; bi++)
#pragma unroll
        for (int mi = 0; mi < 4; mi++) {
            float2 f = fupk(dotp[bi][mi]);
            dsum[bi * 4 + mi] = f.x + f.y;
        }
#pragma unroll
    for (int mi = 0; mi < 4; mi++) {
        float2 f = fupk(ssp[mi]);
        ssv[mi] = f.x + f.y;
    }
    if (us == 1) {
#pragma unroll
        for (int k = 0; k < 16; k++) red[tl * 17 + k] = dsum[k];
        if (bg == 0) {
#pragma unroll
            for (int mi = 0; mi < 4; mi++) ss_red[mg + mi * 16] = ssv[mi];
        }
    }
    __syncthreads();
    if (us == 0) {
#pragma unroll
        for (int k = 0; k < 16; k++) dsum[k] += red[tl * 17 + k];
        if (bg == 0) {
#pragma unroll
            for (int mi = 0; mi < 4; mi++) {
                float s = ss_red[mg + mi * 16] + ssv[mi];
                ss_red[mg + mi * 16] = rsqrtf(fmaxf(s, 1e-12f));
            }
        }
    }
    __syncthreads();
    if (us == 0) {
#pragma unroll
        for (int bi = 0; bi < 4; bi++) {
            int b = bg + bi * 8;
            float hinv = g_hinv[b];
            float v[4];
#pragma unroll
            for (int mi = 0; mi < 4; mi++) {
                int m = mg + mi * 16;
                v[mi] = dsum[bi * 4 + mi] * hinv * ss_red[m];
                out[WR_OFF + (size_t)b * 65536 + m0 + m] = v[mi];
            }
            float pm_t = fmaxf(fmaxf(v[0], v[1]), fmaxf(v[2], v[3]));
            float s_t = expf(v[0] - pm_t) + expf(v[1] - pm_t) +
                        expf(v[2] - pm_t) + expf(v[3] - pm_t);
            pmx[b * 16 + mg] = pm_t;
            psx[b * 16 + mg] = s_t;
        }
    }
    __syncthreads();
    if (t < 32) {
        float pm = -FLT_MAX;
#pragma unroll
        for (int q = 0; q < 16; q++) pm = fmaxf(pm, pmx[t * 16 + q]);
        float s = 0.0f;
#pragma unroll
        for (int q = 0; q < 16; q++) s += psx[t * 16 + q] * expf(pmx[t * 16 + q] - pm);
        g_pm[t * 1024 + blockIdx.x] = pm;
        g_ps[t * 1024 + blockIdx.x] = s;
    }
}

// ---------------- K5: softmax combine (grid 32, one block per b) ----------------
__global__ __launch_bounds__(256) void k_red2()
{
    int b = blockIdx.x;
    int t = threadIdx.x;
    __shared__ float red[256];
    float pm = -FLT_MAX;
#pragma unroll
    for (int k = 0; k < 4; k++)
        pm = fmaxf(pm, g_pm[b * 1024 + t + k * 256]);
    red[t] = pm; __syncthreads();
    for (int st = 128; st > 0; st >>= 1) {
        if (t < st) red[t] = fmaxf(red[t], red[t + st]);
        __syncthreads();
    }
    float gm = red[0];
    __syncthreads();
    float s = 0.0f;
#pragma unroll
    for (int k = 0; k < 4; k++) {
        int idx = b * 1024 + t + k * 256;
        s += g_ps[idx] * expf(g_pm[idx] - gm);
    }
    red[t] = s; __syncthreads();
    for (int st = 128; st > 0; st >>= 1) {
        if (t < st) red[t] += red[t + st];
        __syncthreads();
    }
    if (t == 0) { g_gmax[b] = gm; g_invden[b] = 1.0f / red[0]; }
}

// ---------------- K6: wr (in place over sim), wu_new, order-stat partials ----------------
__global__ __launch_bounds__(256) void k_wr_wu(const float* __restrict__ wu,
                                               const float* __restrict__ wlu,
                                               const float* __restrict__ wr_prev,
                                               const float* __restrict__ wg,
                                               float* __restrict__ out)
{
    int blk = blockIdx.x;             // 1024 = 32 b x 32 chunks
    int b = blk >> 5, mc = blk & 31;
    int t = threadIdx.x;
    size_t base = (size_t)b * 65536 + (size_t)mc * 2048 + (size_t)t * 8;
    float sg = 1.0f / (1.0f + expf(-wg[0]));
    float gm = g_gmax[b], inv = g_invden[b];

    float s1 = FLT_MAX, s2 = FLT_MAX;
    float mv = FLT_MAX; int mi_ = 0x7fffffff;
#pragma unroll
    for (int k = 0; k < 8; k++) {
        size_t idx = base + k;
        float sim = out[WR_OFF + idx];
        float wr = expf(sim - gm) * inv;
        out[WR_OFF + idx] = wr;
        float ww = sg * wr_prev[idx] + (1.0f - sg) * wlu[idx];
        float wun = 0.5f * wu[idx] + wr + ww;
        out[WU_OFF + idx] = wun;
        if (wun < s1) { s2 = s1; s1 = wun; }
        else if (wun < s2) { s2 = wun; }
        int m = (int)(idx - (size_t)b * 65536);
        if (wun < mv || (wun == mv && m < mi_)) { mv = wun; mi_ = m; }
    }
    __shared__ float r1[256], r2[256], rv[256];
    __shared__ int ri_[256];
    r1[t] = s1; r2[t] = s2; rv[t] = mv; ri_[t] = mi_;
    __syncthreads();
    for (int st = 128; st > 0; st >>= 1) {
        if (t < st) {
            float b1 = r1[t + st], b2 = r2[t + st];
            float a1 = r1[t], a2 = r2[t];
            if (b1 < a1) { a2 = fminf(a1, b2); a1 = b1; }
            else         { a2 = fminf(a2, b1); }
            r1[t] = a1; r2[t] = a2;
            float bv = rv[t + st]; int bi2 = ri_[t + st];
            if (bv < rv[t] || (bv == rv[t] && bi2 < ri_[t])) { rv[t] = bv; ri_[t] = bi2; }
        }
        __syncthreads();
    }
    if (t == 0) { g_bv1[blk] = r1[0]; g_bv2[blk] = r2[0]; g_bmv[blk] = rv[0]; g_bmi[blk] = ri_[0]; }
}

__global__ void k_redmin()
{
    int b = threadIdx.x;
    __shared__ int sidx[32];
    if (b < 32) {
        float s1 = FLT_MAX, s2 = FLT_MAX;
        float mv = FLT_MAX; int mi_ = 0x7fffffff;
        for (int p = 0; p < 32; p++) {
            int blk = b * 32 + p;
            float b1 = g_bv1[blk], b2 = g_bv2[blk];
            if (b1 < s1) { s2 = fminf(s1, b2); s1 = b1; }
            else         { s2 = fminf(s2, b1); }
            float bv = g_bmv[blk]; int bi2 = g_bmi[blk];
            if (bv < mv || (bv == mv && bi2 < mi_)) { mv = bv; mi_ = bi2; }
        }
        g_nth[b] = s2;
        sidx[b] = mi_;
    }
    __syncthreads();
    if (b == 0) {
        int m = sidx[0];
        for (int i = 1; i < 32; i++) m = min(m, sidx[i]);
        g_si[0] = m;
    }
}

// ---------------- K7: wlu_new ----------------
__global__ __launch_bounds__(256) void k_wlu(float* __restrict__ out)
{
    int blk = blockIdx.x;
    int b = blk >> 5, mc = blk & 31;
    size_t base = (size_t)b * 65536 + (size_t)mc * 2048 + (size_t)threadIdx.x * 8;
    float nth = g_nth[b];
#pragma unroll
    for (int k = 0; k < 8; k++)
        out[WLU_OFF + base + k] = (out[WU_OFF + base + k] <= nth) ? 1.0f : 0.0f;
}

// ---------------- K8: keep-row fixup on mem_new ----------------
__global__ void k_fixrow(const float* __restrict__ mb, float* __restrict__ out)
{
    int m = g_si[0];
    for (int u = threadIdx.x; u < 1024; u += blockDim.x)
        out[MEM_OFF + (size_t)m * 1024 + u] -= mb[(size_t)m * 1024 + u];
}

// ---------------- K9: r = wr @ membank (split-K), 8b x 4u tile, grid 512 -------------
__global__ __launch_bounds__(256) void k_r(const float* __restrict__ mb,
                                           const float* __restrict__ out)
{
    __shared__ __align__(16) float wr_t[64][36];   // 144B stride, 16-aligned
    int slice = blockIdx.x >> 2;
    int ut = blockIdx.x & 3;
    int t = threadIdx.x;
    int tu = t & 63;
    int b0 = (t >> 6) * 8;
    int u = ut * 256 + tu * 4;
    int mbase = slice * 512;

    ull accp[4][4];
#pragma unroll
    for (int i = 0; i < 4; i++)
#pragma unroll
        for (int j = 0; j < 4; j++) accp[i][j] = 0ULL;

    for (int mc = 0; mc < 512; mc += 64) {
#pragma unroll
        for (int i = 0; i < 8; i++) {
            int e = t + i * 256;
            int b = e >> 6, mm = e & 63;
            wr_t[mm][b] = out[WR_OFF + (size_t)b * 65536 + mbase + mc + mm];
        }
        __syncthreads();
#pragma unroll 8
        for (int mm = 0; mm < 64; mm++) {
            float4 v = *(const float4*)&mb[(size_t)(mbase + mc + mm) * 1024 + u];
            ull vd0 = fdup(v.x), vd1 = fdup(v.y), vd2 = fdup(v.z), vd3 = fdup(v.w);
            ulonglong2 w01 = *(const ulonglong2*)&wr_t[mm][b0];
            ulonglong2 w23 = *(const ulonglong2*)&wr_t[mm][b0 + 4];
            ffma2(accp[0][0], w01.x, vd0); ffma2(accp[0][1], w01.x, vd1);
            ffma2(accp[0][2], w01.x, vd2); ffma2(accp[0][3], w01.x, vd3);
            ffma2(accp[1][0], w01.y, vd0); ffma2(accp[1][1], w01.y, vd1);
            ffma2(accp[1][2], w01.y, vd2); ffma2(accp[1][3], w01.y, vd3);
            ffma2(accp[2][0], w23.x, vd0); ffma2(accp[2][1], w23.x, vd1);
            ffma2(accp[2][2], w23.x, vd2); ffma2(accp[2][3], w23.x, vd3);
            ffma2(accp[3][0], w23.y, vd0); ffma2(accp[3][1], w23.y, vd1);
            ffma2(accp[3][2], w23.y, vd2); ffma2(accp[3][3], w23.y, vd3);
        }
        __syncthreads();
    }
#pragma unroll
    for (int bp = 0; bp < 4; bp++) {
        float2 f0 = fupk(accp[bp][0]), f1 = fupk(accp[bp][1]);
        float2 f2 = fupk(accp[bp][2]), f3 = fupk(accp[bp][3]);
        size_t base = ((size_t)slice * 32 + b0 + bp * 2) * 1024 + u;
        *(float4*)&g_rp[base]        = make_float4(f0.x, f1.x, f2.x, f3.x);
        *(float4*)&g_rp[base + 1024] = make_float4(f0.y, f1.y, f2.y, f3.y);
    }
}

__global__ __launch_bounds__(256) void k_rred(float* __restrict__ out)
{
    int idx = blockIdx.x * 256 + threadIdx.x;   // 0..32767
    float s = 0;
    for (int sl = 0; sl < 128; sl++) s += g_rp[(size_t)sl * 32768 + idx];
    out[R_OFF + idx] = s;
}

// ---------------- launcher ----------------
extern "C" void kernel_launch(void* const* d_in, const int* in_sizes, int n_in,
                              void* d_out, int out_size)
{
    const float* x        = (const float*)d_in[0];
    const float* h_tm1    = (const float*)d_in[1];
    const float* c_tm1    = (const float*)d_in[2];
    const float* r_tm1    = (const float*)d_in[3];
    const float* membank  = (const float*)d_in[4];
    const float* wu       = (const float*)d_in[5];
    const float* wlu      = (const float*)d_in[6];
    const float* wr_prev  = (const float*)d_in[7];
    const float* Wk       = (const float*)d_in[8];
    const float* RK       = (const float*)d_in[9];
    const float* bias     = (const float*)d_in[10];
    const float* wgate    = (const float*)d_in[11];
    float* out = (float*)d_out;

    cudaFuncSetAttribute(k_sim_mem, cudaFuncAttributeMaxDynamicSharedMemorySize, K4_SMEM);

    k_gemm<<<160, 256>>>(x, h_tm1, r_tm1, Wk, RK, bias);
    k_gates<<<128, 256>>>(c_tm1, out);
    k_hinv<<<1, 32>>>();
    k_sim_mem<<<1024, 256, K4_SMEM>>>(membank, wr_prev, wlu, wgate, out);
    k_red2<<<32, 256>>>();
    k_wr_wu<<<1024, 256>>>(wu, wlu, wr_prev, wgate, out);
    k_redmin<<<1, 32>>>();
    k_wlu<<<1024, 256>>>(out);
    k_fixrow<<<1, 256>>>(membank, out);
    k_r<<<512, 256>>>(membank, out);
    k_rred<<<128, 256>>>(out);
}

// round 17
// speedup vs baseline: 1.1617x; 1.0331x over previous
#include <cuda_runtime.h>
#include <math.h>
#include <float.h>

#define BB 32
#define UUU 1024
#define MMM 65536

// output offsets (floats)
#define R_OFF   ((size_t)0)
#define H_OFF   ((size_t)32768)
#define C_OFF   ((size_t)65536)
#define MEM_OFF ((size_t)98304)
#define WU_OFF  ((size_t)67207168)
#define WLU_OFF ((size_t)69304320)
#define WR_OFF  ((size_t)71401472)

typedef unsigned long long ull;

__device__ __forceinline__ ull fdup(float x) {
    ull r; asm("mov.b64 %0, {%1,%1};" : "=l"(r) : "f"(x)); return r;
}
__device__ __forceinline__ void ffma2(ull &d, ull a, ull b) {
    asm("fma.rn.f32x2 %0, %1, %2, %0;" : "+l"(d) : "l"(a), "l"(b));
}
__device__ __forceinline__ float2 fupk(ull v) {
    float2 f; asm("mov.b64 {%0,%1}, %2;" : "=f"(f.x), "=f"(f.y) : "l"(v)); return f;
}

// ---------------- scratch (device globals, no allocation) ----------------
__device__ float g_zp[4 * 32 * 5120];        // gate GEMM k-split partials
__device__ float g_h[BB * UUU];              // h (post-activation)
__device__ float g_hss[128];                 // partial sums of h^2
__device__ float g_hinv[BB];                 // 1/||h||
__device__ float g_pm[32 * 1024], g_ps[32 * 1024];  // softmax partials [b][block]
__device__ float g_gmax[BB], g_invden[BB];
__device__ float g_bv1[1024], g_bv2[1024], g_bmv[1024];
__device__ int   g_bmi[1024];
__device__ float g_nth[BB];
__device__ int   g_si[1];
__device__ float g_rp[(size_t)128 * BB * UUU]; // r split-K partials

__device__ __forceinline__ float hsig(float v) {
    return fminf(fmaxf(0.2f * v + 0.5f, 0.0f), 1.0f);
}

// ---------------- K1: gate GEMMs (x@W + h@R1 fused; r@R2), k-split 4 ----------------
__global__ __launch_bounds__(256) void k_gemm(
    const float* __restrict__ x, const float* __restrict__ h,
    const float* __restrict__ r, const float* __restrict__ W,
    const float* __restrict__ RK, const float* __restrict__ bias)
{
    __shared__ ull A2[32 * 34];                   // dup-packed A
    __shared__ __align__(16) float W_s[32][132];
    int jb = blockIdx.x >> 2;
    int ks = blockIdx.x & 3;
    int t = threadIdx.x;
    int b0 = (t >> 5) * 4;
    int j0 = (t & 31) * 4;
    int jbase = jb * 128;

    ull accp[4][2];
#pragma unroll
    for (int i = 0; i < 4; i++) { accp[i][0] = 0ULL; accp[i][1] = 0ULL; }

    int nsrc = (jb < 32) ? 2 : 1;
    int kbase = ks * 256;
    for (int s = 0; s < nsrc; s++) {
        const float* A; const float* Wm; int ldw;
        if (jb < 32) {
            if (s == 0) { A = x; Wm = W;  ldw = 4096; }
            else        { A = h; Wm = RK; ldw = 5120; }
        } else          { A = r; Wm = RK; ldw = 5120; }

        for (int kc = 0; kc < 256; kc += 32) {
#pragma unroll
            for (int i = 0; i < 4; i++) {
                int e = t + i * 256;
                A2[(e >> 5) * 34 + (e & 31)] =
                    fdup(A[(e >> 5) * 1024 + kbase + kc + (e & 31)]);
            }
#pragma unroll
            for (int i = 0; i < 16; i++) {
                int e = t + i * 256;
                int kk = e >> 7, j = e & 127;
                W_s[kk][j] = Wm[(size_t)(kbase + kc + kk) * ldw + jbase + j];
            }
            __syncthreads();
#pragma unroll
            for (int kk = 0; kk < 32; kk++) {
                ull wp0 = *(const ull*)&W_s[kk][j0];
                ull wp1 = *(const ull*)&W_s[kk][j0 + 2];
#pragma unroll
                for (int i = 0; i < 4; i++) {
                    ull ad = A2[(b0 + i) * 34 + kk];
                    ffma2(accp[i][0], ad, wp0);
                    ffma2(accp[i][1], ad, wp1);
                }
            }
            __syncthreads();
        }
    }
#pragma unroll
    for (int i = 0; i < 4; i++) {
#pragma unroll
        for (int jp = 0; jp < 2; jp++) {
            float2 f = fupk(accp[i][jp]);
            int j = jbase + j0 + jp * 2;
            float v0 = f.x, v1 = f.y;
            if (ks == 0 && jb < 32) { v0 += bias[j]; v1 += bias[j + 1]; }
            g_zp[((ks * 32) + (b0 + i)) * 5120 + j]     = v0;
            g_zp[((ks * 32) + (b0 + i)) * 5120 + j + 1] = v1;
        }
    }
}

// ---------------- K2: reduce partials, activations, h, c, h^2 partials ----------------
__global__ __launch_bounds__(256) void k_gates(const float* __restrict__ c_tm1,
                                               float* __restrict__ out)
{
    int blk = blockIdx.x;            // 128
    int b = blk >> 2, uc = blk & 3;
    int u = uc * 256 + threadIdx.x;
    float zi = 0, zf = 0, zc = 0, zo = 0, ri = 0;
#pragma unroll
    for (int s = 0; s < 4; s++) {
        const float* p = &g_zp[(s * 32 + b) * 5120];
        zi += p[u]; zf += p[1024 + u]; zc += p[2048 + u]; zo += p[3072 + u]; ri += p[4096 + u];
    }
    float ig = hsig(zi + ri), fg = hsig(zf), og = hsig(zo);
    float c = fg * c_tm1[b * 1024 + u] + ig * tanhf(zc);
    float hh = og * tanhf(c);
    out[C_OFF + b * 1024 + u] = c;
    out[H_OFF + b * 1024 + u] = hh;
    g_h[b * 1024 + u] = hh;

    __shared__ float red[256];
    red[threadIdx.x] = hh * hh;
    __syncthreads();
    for (int s = 128; s > 0; s >>= 1) {
        if (threadIdx.x < s) red[threadIdx.x] += red[threadIdx.x + s];
        __syncthreads();
    }
    if (threadIdx.x == 0) g_hss[blk] = red[0];
}

__global__ void k_hinv() {
    int b = threadIdx.x;
    if (b < 32) {
        float s = g_hss[b * 4] + g_hss[b * 4 + 1] + g_hss[b * 4 + 2] + g_hss[b * 4 + 3];
        g_hinv[b] = rsqrtf(fmaxf(s, 1e-12f));
    }
}

// ---------------- K4: fused membank pass (dots + ss + mem_new + softmax partials) ----
// layout: ww_f (float[32*132]) | h_s (float[32*132]) | mb_s (float[64*132])
#define K4_STR 132
#define K4_SMEM ((32*K4_STR + 32*K4_STR + 64*K4_STR) * 4)

__global__ __launch_bounds__(256, 2) void k_sim_mem(const float* __restrict__ mb,
                                                    const float* __restrict__ wr_prev,
                                                    const float* __restrict__ wlu,
                                                    const float* __restrict__ wg,
                                                    float* __restrict__ out)
{
    extern __shared__ __align__(16) char smem_raw[];
    float* ww_f = (float*)smem_raw;                                    // [32][132] plain
    float* h_s  = (float*)(smem_raw + 32 * K4_STR * 4);                // [32][132]
    float* mb_s = (float*)(smem_raw + 64 * K4_STR * 4);                // [64][132]
    float* red    = mb_s;                                              // alias (epilogue)
    float* ss_red = mb_s + 128 * 17;
    float* pmx    = mb_s + 2304;                                       // [32][16]
    float* psx    = mb_s + 2304 + 512;                                 // [32][16]

    int m0 = blockIdx.x * 64;
    int t = threadIdx.x;

    // ww fill: plain floats
    float sg = 1.0f / (1.0f + expf(-wg[0]));
#pragma unroll
    for (int i = 0; i < 8; i++) {
        int e = t + i * 256;
        int b = e >> 6, m = e & 63;
        size_t gi = (size_t)b * 65536 + m0 + m;
        ww_f[b * K4_STR + m] = sg * wr_prev[gi] + (1.0f - sg) * wlu[gi];
    }

    int tl = t & 127, us = t >> 7;
    int bg = tl & 7, mg = tl >> 3;      // dots: b rows bg+{0,8,16,24}, m rows mg+{0,16,32,48}
    int ug2 = t & 31, mg8 = t >> 5;     // memnew: m rows mg8*8+{0..7}, u cols ug2*4+{0..3}

    ull dotp[4][4];
    ull ssp[4];
#pragma unroll
    for (int i = 0; i < 4; i++) {
#pragma unroll
        for (int j = 0; j < 4; j++) dotp[i][j] = 0ULL;
        ssp[i] = 0ULL;
    }

    for (int uc = 0; uc < 1024; uc += 128) {
        __syncthreads();
        // fill h_s [32][128]
#pragma unroll
        for (int i = 0; i < 4; i++) {
            int f = t + i * 256;
            int row = f >> 5, c = (f & 31) * 4;
            *(float4*)&h_s[row * K4_STR + c] = *(const float4*)&g_h[row * 1024 + uc + c];
        }
        // fill mb_s [64][128]
#pragma unroll
        for (int i = 0; i < 8; i++) {
            int f = t + i * 256;
            int row = f >> 5, c = (f & 31) * 4;
            *(float4*)&mb_s[row * K4_STR + c] =
                *(const float4*)&mb[(size_t)(m0 + row) * 1024 + uc + c];
        }
        __syncthreads();

        // ---- dots: each thread 4b x 4m, its u-half (16 of 32 u4-steps) ----
#pragma unroll 4
        for (int u4 = us * 16; u4 < us * 16 + 16; u4++) {
            ulonglong2 hp[4], mp[4];
#pragma unroll
            for (int bi = 0; bi < 4; bi++)
                hp[bi] = *(const ulonglong2*)&h_s[(bg + bi * 8) * K4_STR + u4 * 4];
#pragma unroll
            for (int mi = 0; mi < 4; mi++)
                mp[mi] = *(const ulonglong2*)&mb_s[(mg + mi * 16) * K4_STR + u4 * 4];
#pragma unroll
            for (int bi = 0; bi < 4; bi++)
#pragma unroll
                for (int mi = 0; mi < 4; mi++) {
                    ffma2(dotp[bi][mi], hp[bi].x, mp[mi].x);
                    ffma2(dotp[bi][mi], hp[bi].y, mp[mi].y);
                }
            if (bg == 0) {
#pragma unroll
                for (int mi = 0; mi < 4; mi++) {
                    ffma2(ssp[mi], mp[mi].x, mp[mi].x);
                    ffma2(ssp[mi], mp[mi].y, mp[mi].y);
                }
            }
        }

        // ---- mem_new: each thread 8m x 4u; ww = 2 uniform float4 loads + fdup ----
        ull acc[8][2];
#pragma unroll
        for (int mi = 0; mi < 8; mi++) {
            ulonglong2 a = *(const ulonglong2*)&mb_s[(mg8 * 8 + mi) * K4_STR + ug2 * 4];
            acc[mi][0] = a.x; acc[mi][1] = a.y;
        }
#pragma unroll 4
        for (int b = 0; b < 32; b++) {
            float4 w0 = *(const float4*)&ww_f[b * K4_STR + mg8 * 8];
            float4 w1 = *(const float4*)&ww_f[b * K4_STR + mg8 * 8 + 4];
            ull wd0 = fdup(w0.x), wd1 = fdup(w0.y), wd2 = fdup(w0.z), wd3 = fdup(w0.w);
            ull wd4 = fdup(w1.x), wd5 = fdup(w1.y), wd6 = fdup(w1.z), wd7 = fdup(w1.w);
            ulonglong2 hh = *(const ulonglong2*)&h_s[b * K4_STR + ug2 * 4];
            ffma2(acc[0][0], wd0, hh.x); ffma2(acc[0][1], wd0, hh.y);
            ffma2(acc[1][0], wd1, hh.x); ffma2(acc[1][1], wd1, hh.y);
            ffma2(acc[2][0], wd2, hh.x); ffma2(acc[2][1], wd2, hh.y);
            ffma2(acc[3][0], wd3, hh.x); ffma2(acc[3][1], wd3, hh.y);
            ffma2(acc[4][0], wd4, hh.x); ffma2(acc[4][1], wd4, hh.y);
            ffma2(acc[5][0], wd5, hh.x); ffma2(acc[5][1], wd5, hh.y);
            ffma2(acc[6][0], wd6, hh.x); ffma2(acc[6][1], wd6, hh.y);
            ffma2(acc[7][0], wd7, hh.x); ffma2(acc[7][1], wd7, hh.y);
        }
#pragma unroll
        for (int mi = 0; mi < 8; mi++) {
            size_t o = MEM_OFF + (size_t)(m0 + mg8 * 8 + mi) * 1024 + uc + ug2 * 4;
            ulonglong2 s; s.x = acc[mi][0]; s.y = acc[mi][1];
            *(ulonglong2*)&out[o] = s;
        }
    }

    // ---- epilogue: combine u-halves, normalize, store sim, softmax partials ----
    __syncthreads();
    float dsum[16], ssv[4];
#pragma unroll
    for (int bi = 0; bi < 4; bi++)
#pragma unroll
        for (int mi = 0; mi < 4; mi++) {
            float2 f = fupk(dotp[bi][mi]);
            dsum[bi * 4 + mi] = f.x + f.y;
        }
#pragma unroll
    for (int mi = 0; mi < 4; mi++) {
        float2 f = fupk(ssp[mi]);
        ssv[mi] = f.x + f.y;
    }
    if (us == 1) {
#pragma unroll
        for (int k = 0; k < 16; k++) red[tl * 17 + k] = dsum[k];
        if (bg == 0) {
#pragma unroll
            for (int mi = 0; mi < 4; mi++) ss_red[mg + mi * 16] = ssv[mi];
        }
    }
    __syncthreads();
    if (us == 0) {
#pragma unroll
        for (int k = 0; k < 16; k++) dsum[k] += red[tl * 17 + k];
        if (bg == 0) {
#pragma unroll
            for (int mi = 0; mi < 4; mi++) {
                float s = ss_red[mg + mi * 16] + ssv[mi];
                ss_red[mg + mi * 16] = rsqrtf(fmaxf(s, 1e-12f));
            }
        }
    }
    __syncthreads();
    if (us == 0) {
#pragma unroll
        for (int bi = 0; bi < 4; bi++) {
            int b = bg + bi * 8;
            float hinv = g_hinv[b];
            float v[4];
#pragma unroll
            for (int mi = 0; mi < 4; mi++) {
                int m = mg + mi * 16;
                v[mi] = dsum[bi * 4 + mi] * hinv * ss_red[m];
                out[WR_OFF + (size_t)b * 65536 + m0 + m] = v[mi];
            }
            float pm_t = fmaxf(fmaxf(v[0], v[1]), fmaxf(v[2], v[3]));
            float s_t = expf(v[0] - pm_t) + expf(v[1] - pm_t) +
                        expf(v[2] - pm_t) + expf(v[3] - pm_t);
            pmx[b * 16 + mg] = pm_t;
            psx[b * 16 + mg] = s_t;
        }
    }
    __syncthreads();
    if (t < 32) {
        float pm = -FLT_MAX;
#pragma unroll
        for (int q = 0; q < 16; q++) pm = fmaxf(pm, pmx[t * 16 + q]);
        float s = 0.0f;
#pragma unroll
        for (int q = 0; q < 16; q++) s += psx[t * 16 + q] * expf(pmx[t * 16 + q] - pm);
        g_pm[t * 1024 + blockIdx.x] = pm;
        g_ps[t * 1024 + blockIdx.x] = s;
    }
}

// ---------------- K5: softmax combine (grid 32, one block per b) ----------------
__global__ __launch_bounds__(256) void k_red2()
{
    int b = blockIdx.x;
    int t = threadIdx.x;
    __shared__ float red[256];
    float pm = -FLT_MAX;
#pragma unroll
    for (int k = 0; k < 4; k++)
        pm = fmaxf(pm, g_pm[b * 1024 + t + k * 256]);
    red[t] = pm; __syncthreads();
    for (int st = 128; st > 0; st >>= 1) {
        if (t < st) red[t] = fmaxf(red[t], red[t + st]);
        __syncthreads();
    }
    float gm = red[0];
    __syncthreads();
    float s = 0.0f;
#pragma unroll
    for (int k = 0; k < 4; k++) {
        int idx = b * 1024 + t + k * 256;
        s += g_ps[idx] * expf(g_pm[idx] - gm);
    }
    red[t] = s; __syncthreads();
    for (int st = 128; st > 0; st >>= 1) {
        if (t < st) red[t] += red[t + st];
        __syncthreads();
    }
    if (t == 0) { g_gmax[b] = gm; g_invden[b] = 1.0f / red[0]; }
}

// ---------------- K6: wr (in place over sim), wu_new, order-stat partials ----------------
__global__ __launch_bounds__(256) void k_wr_wu(const float* __restrict__ wu,
                                               const float* __restrict__ wlu,
                                               const float* __restrict__ wr_prev,
                                               const float* __restrict__ wg,
                                               float* __restrict__ out)
{
    int blk = blockIdx.x;             // 1024 = 32 b x 32 chunks
    int b = blk >> 5, mc = blk & 31;
    int t = threadIdx.x;
    size_t base = (size_t)b * 65536 + (size_t)mc * 2048 + (size_t)t * 8;
    float sg = 1.0f / (1.0f + expf(-wg[0]));
    float gm = g_gmax[b], inv = g_invden[b];

    float s1 = FLT_MAX, s2 = FLT_MAX;
    float mv = FLT_MAX; int mi_ = 0x7fffffff;
#pragma unroll
    for (int k = 0; k < 8; k++) {
        size_t idx = base + k;
        float sim = out[WR_OFF + idx];
        float wr = expf(sim - gm) * inv;
        out[WR_OFF + idx] = wr;
        float ww = sg * wr_prev[idx] + (1.0f - sg) * wlu[idx];
        float wun = 0.5f * wu[idx] + wr + ww;
        out[WU_OFF + idx] = wun;
        if (wun < s1) { s2 = s1; s1 = wun; }
        else if (wun < s2) { s2 = wun; }
        int m = (int)(idx - (size_t)b * 65536);
        if (wun < mv || (wun == mv && m < mi_)) { mv = wun; mi_ = m; }
    }
    __shared__ float r1[256], r2[256], rv[256];
    __shared__ int ri_[256];
    r1[t] = s1; r2[t] = s2; rv[t] = mv; ri_[t] = mi_;
    __syncthreads();
    for (int st = 128; st > 0; st >>= 1) {
        if (t < st) {
            float b1 = r1[t + st], b2 = r2[t + st];
            float a1 = r1[t], a2 = r2[t];
            if (b1 < a1) { a2 = fminf(a1, b2); a1 = b1; }
            else         { a2 = fminf(a2, b1); }
            r1[t] = a1; r2[t] = a2;
            float bv = rv[t + st]; int bi2 = ri_[t + st];
            if (bv < rv[t] || (bv == rv[t] && bi2 < ri_[t])) { rv[t] = bv; ri_[t] = bi2; }
        }
        __syncthreads();
    }
    if (t == 0) { g_bv1[blk] = r1[0]; g_bv2[blk] = r2[0]; g_bmv[blk] = rv[0]; g_bmi[blk] = ri_[0]; }
}

__global__ void k_redmin()
{
    int b = threadIdx.x;
    __shared__ int sidx[32];
    if (b < 32) {
        float s1 = FLT_MAX, s2 = FLT_MAX;
        float mv = FLT_MAX; int mi_ = 0x7fffffff;
        for (int p = 0; p < 32; p++) {
            int blk = b * 32 + p;
            float b1 = g_bv1[blk], b2 = g_bv2[blk];
            if (b1 < s1) { s2 = fminf(s1, b2); s1 = b1; }
            else         { s2 = fminf(s2, b1); }
            float bv = g_bmv[blk]; int bi2 = g_bmi[blk];
            if (bv < mv || (bv == mv && bi2 < mi_)) { mv = bv; mi_ = bi2; }
        }
        g_nth[b] = s2;
        sidx[b] = mi_;
    }
    __syncthreads();
    if (b == 0) {
        int m = sidx[0];
        for (int i = 1; i < 32; i++) m = min(m, sidx[i]);
        g_si[0] = m;
    }
}

// ---------------- K7: wlu_new ----------------
__global__ __launch_bounds__(256) void k_wlu(float* __restrict__ out)
{
    int blk = blockIdx.x;
    int b = blk >> 5, mc = blk & 31;
    size_t base = (size_t)b * 65536 + (size_t)mc * 2048 + (size_t)threadIdx.x * 8;
    float nth = g_nth[b];
#pragma unroll
    for (int k = 0; k < 8; k++)
        out[WLU_OFF + base + k] = (out[WU_OFF + base + k] <= nth) ? 1.0f : 0.0f;
}

// ---------------- K8: keep-row fixup on mem_new ----------------
__global__ void k_fixrow(const float* __restrict__ mb, float* __restrict__ out)
{
    int m = g_si[0];
    for (int u = threadIdx.x; u < 1024; u += blockDim.x)
        out[MEM_OFF + (size_t)m * 1024 + u] -= mb[(size_t)m * 1024 + u];
}

// ---------------- K9: r = wr @ membank (split-K), 8b x 4u, 4-deep load batching ------
__global__ __launch_bounds__(256) void k_r(const float* __restrict__ mb,
                                           const float* __restrict__ out)
{
    __shared__ __align__(16) float wr_t[64][36];   // 144B stride, 16-aligned
    int slice = blockIdx.x >> 2;
    int ut = blockIdx.x & 3;
    int t = threadIdx.x;
    int tu = t & 63;
    int b0 = (t >> 6) * 8;
    int u = ut * 256 + tu * 4;
    int mbase = slice * 512;

    ull accp[4][4];
#pragma unroll
    for (int i = 0; i < 4; i++)
#pragma unroll
        for (int j = 0; j < 4; j++) accp[i][j] = 0ULL;

    for (int mc = 0; mc < 512; mc += 64) {
#pragma unroll
        for (int i = 0; i < 8; i++) {
            int e = t + i * 256;
            int b = e >> 6, mm = e & 63;
            wr_t[mm][b] = out[WR_OFF + (size_t)b * 65536 + mbase + mc + mm];
        }
        __syncthreads();
#pragma unroll
        for (int mm = 0; mm < 64; mm += 4) {
            const float* p = &mb[(size_t)(mbase + mc + mm) * 1024 + u];
            float4 v0 = *(const float4*)(p);
            float4 v1 = *(const float4*)(p + 1024);
            float4 v2 = *(const float4*)(p + 2048);
            float4 v3 = *(const float4*)(p + 3072);
#pragma unroll
            for (int q = 0; q < 4; q++) {
                float4 v = (q == 0) ? v0 : (q == 1) ? v1 : (q == 2) ? v2 : v3;
                int m2 = mm + q;
                ull vd0 = fdup(v.x), vd1 = fdup(v.y), vd2 = fdup(v.z), vd3 = fdup(v.w);
                ulonglong2 w01 = *(const ulonglong2*)&wr_t[m2][b0];
                ulonglong2 w23 = *(const ulonglong2*)&wr_t[m2][b0 + 4];
                ffma2(accp[0][0], w01.x, vd0); ffma2(accp[0][1], w01.x, vd1);
                ffma2(accp[0][2], w01.x, vd2); ffma2(accp[0][3], w01.x, vd3);
                ffma2(accp[1][0], w01.y, vd0); ffma2(accp[1][1], w01.y, vd1);
                ffma2(accp[1][2], w01.y, vd2); ffma2(accp[1][3], w01.y, vd3);
                ffma2(accp[2][0], w23.x, vd0); ffma2(accp[2][1], w23.x, vd1);
                ffma2(accp[2][2], w23.x, vd2); ffma2(accp[2][3], w23.x, vd3);
                ffma2(accp[3][0], w23.y, vd0); ffma2(accp[3][1], w23.y, vd1);
                ffma2(accp[3][2], w23.y, vd2); ffma2(accp[3][3], w23.y, vd3);
            }
        }
        __syncthreads();
    }
#pragma unroll
    for (int bp = 0; bp < 4; bp++) {
        float2 f0 = fupk(accp[bp][0]), f1 = fupk(accp[bp][1]);
        float2 f2 = fupk(accp[bp][2]), f3 = fupk(accp[bp][3]);
        size_t base = ((size_t)slice * 32 + b0 + bp * 2) * 1024 + u;
        *(float4*)&g_rp[base]        = make_float4(f0.x, f1.x, f2.x, f3.x);
        *(float4*)&g_rp[base + 1024] = make_float4(f0.y, f1.y, f2.y, f3.y);
    }
}

__global__ __launch_bounds__(256) void k_rred(float* __restrict__ out)
{
    int idx = (blockIdx.x * 256 + threadIdx.x) * 4;   // 0..32764, float4 each
    float4 s = make_float4(0.f, 0.f, 0.f, 0.f);
    for (int sl = 0; sl < 128; sl++) {
        float4 v = *(const float4*)&g_rp[(size_t)sl * 32768 + idx];
        s.x += v.x; s.y += v.y; s.z += v.z; s.w += v.w;
    }
    *(float4*)&out[R_OFF + idx] = s;
}

// ---------------- launcher ----------------
extern "C" void kernel_launch(void* const* d_in, const int* in_sizes, int n_in,
                              void* d_out, int out_size)
{
    const float* x        = (const float*)d_in[0];
    const float* h_tm1    = (const float*)d_in[1];
    const float* c_tm1    = (const float*)d_in[2];
    const float* r_tm1    = (const float*)d_in[3];
    const float* membank  = (const float*)d_in[4];
    const float* wu       = (const float*)d_in[5];
    const float* wlu      = (const float*)d_in[6];
    const float* wr_prev  = (const float*)d_in[7];
    const float* Wk       = (const float*)d_in[8];
    const float* RK       = (const float*)d_in[9];
    const float* bias     = (const float*)d_in[10];
    const float* wgate    = (const float*)d_in[11];
    float* out = (float*)d_out;

    cudaFuncSetAttribute(k_sim_mem, cudaFuncAttributeMaxDynamicSharedMemorySize, K4_SMEM);

    k_gemm<<<160, 256>>>(x, h_tm1, r_tm1, Wk, RK, bias);
    k_gates<<<128, 256>>>(c_tm1, out);
    k_hinv<<<1, 32>>>();
    k_sim_mem<<<1024, 256, K4_SMEM>>>(membank, wr_prev, wlu, wgate, out);
    k_red2<<<32, 256>>>();
    k_wr_wu<<<1024, 256>>>(wu, wlu, wr_prev, wgate, out);
    k_redmin<<<1, 32>>>();
    k_wlu<<<1024, 256>>>(out);
    k_fixrow<<<1, 256>>>(membank, out);
    k_r<<<512, 256>>>(membank, out);
    k_rred<<<32, 256>>>(out);
}